// round 3
// baseline (speedup 1.0000x reference)
#include <cuda_runtime.h>
#include <cuda_bf16.h>

constexpr int B = 65536;
constexpr int C = 1000;
constexpr float INV_NEG_T = -1.0f / 0.3f;   // -1/TEMPERATURE
constexpr int SPLIT = 2;                     // blocks per class (load smoothing)

// Scratch (device globals — no allocation allowed)
__device__ int    g_count[C];
__device__ int    g_offset[C + 1];
__device__ int    g_cursor[C];
__device__ int    g_rows[B];
__device__ double g_part[C * SPLIT];

// ---------------------------------------------------------------------------
// Binning: counting sort of row indices by target class.
// ---------------------------------------------------------------------------
__global__ void zero_kernel() {
    const int i = blockIdx.x * blockDim.x + threadIdx.x;
    if (i < C) g_count[i] = 0;
}

__global__ void count_kernel(const int* __restrict__ targets) {
    const int i = blockIdx.x * blockDim.x + threadIdx.x;
    if (i < B) {
        int t = targets[i];
        t = (t < 0) ? 0 : ((t >= C) ? C - 1 : t);
        atomicAdd(&g_count[t], 1);
    }
}

__global__ void scan_kernel() {   // one block, 1024 threads: exclusive scan of counts
    __shared__ int s[1024];
    const int i = threadIdx.x;
    const int v = (i < C) ? g_count[i] : 0;
    s[i] = v;
    __syncthreads();
    #pragma unroll
    for (int d = 1; d < 1024; d <<= 1) {
        int x = (i >= d) ? s[i - d] : 0;
        __syncthreads();
        s[i] += x;
        __syncthreads();
    }
    if (i < C) {
        const int excl = s[i] - v;
        g_offset[i] = excl;
        g_cursor[i] = excl;
        if (i == C - 1) g_offset[C] = s[i];
    }
}

__global__ void scatter_kernel(const int* __restrict__ targets) {
    const int i = blockIdx.x * blockDim.x + threadIdx.x;
    if (i < B) {
        int t = targets[i];
        t = (t < 0) ? 0 : ((t >= C) ? C - 1 : t);
        const int pos = atomicAdd(&g_cursor[t], 1);
        g_rows[pos] = i;
    }
}

// ---------------------------------------------------------------------------
// Main: one block per (class, half). Computes raw exp(-sim/T) for the class
// into SMEM once, then streams its assigned logits rows from DRAM:
//   loss_b = log(sum_c exp(x_bc)) - dot(e, x_b) / sum_c(e_c)
// ---------------------------------------------------------------------------
__global__ __launch_bounds__(256)
void soft_ce_main_kernel(const float* __restrict__ logits,
                         const float* __restrict__ sim) {
    const int t    = blockIdx.x / SPLIT;
    const int part = blockIdx.x % SPLIT;

    __shared__ __align__(16) float sS[C];   // raw exp values (unnormalized)
    __shared__ float red[256];
    __shared__ double wacc[8];

    // Phase 1: e_c = exp(-sim[t,c]/T) into SMEM + block sum
    const float* srow = sim + (size_t)t * C;
    float lsum = 0.0f;
    for (int i = threadIdx.x; i < C; i += 256) {
        const float e = __expf(srow[i] * INV_NEG_T);
        sS[i] = e;
        lsum += e;
    }
    red[threadIdx.x] = lsum;
    __syncthreads();
    for (int s = 128; s > 0; s >>= 1) {
        if (threadIdx.x < s) red[threadIdx.x] += red[threadIdx.x + s];
        __syncthreads();
    }
    const float inv_esum = 1.0f / red[0];

    // Phase 2: stream assigned rows, one warp per row
    const int warp = threadIdx.x >> 5;
    const int lane = threadIdx.x & 31;
    const int start = g_offset[t];
    const int end   = g_offset[t + 1];

    double acc = 0.0;
    for (int r = start + part * 8 + warp; r < end; r += SPLIT * 8) {
        const int row = g_rows[r];
        const float4* lp = (const float4*)(logits + (size_t)row * C);

        float sum = 0.0f, dot = 0.0f;
        #pragma unroll
        for (int k = 0; k < 8; k++) {
            const int i = lane + k * 32;   // 250 float4 per row
            if (i < 250) {
                const float4 x = lp[i];
                const float4 s = *(const float4*)(sS + 4 * i);
                sum += __expf(x.x) + __expf(x.y) + __expf(x.z) + __expf(x.w);
                dot += s.x * x.x + s.y * x.y + s.z * x.z + s.w * x.w;
            }
        }
        #pragma unroll
        for (int o = 16; o; o >>= 1) {
            sum += __shfl_xor_sync(0xffffffffu, sum, o);
            dot += __shfl_xor_sync(0xffffffffu, dot, o);
        }
        if (lane == 0)
            acc += (double)(__logf(sum) - dot * inv_esum);
    }

    if (lane == 0) wacc[warp] = acc;
    __syncthreads();
    if (threadIdx.x == 0) {
        double bacc = 0.0;
        #pragma unroll
        for (int w = 0; w < 8; w++) bacc += wacc[w];
        g_part[blockIdx.x] = bacc;
    }
}

// ---------------------------------------------------------------------------
// Final reduce: sum C*SPLIT doubles -> mean loss (float scalar).
// ---------------------------------------------------------------------------
__global__ void final_reduce_kernel(float* __restrict__ out) {
    __shared__ double red[256];
    double acc = 0.0;
    for (int i = threadIdx.x; i < C * SPLIT; i += 256)
        acc += g_part[i];
    red[threadIdx.x] = acc;
    __syncthreads();
    for (int s = 128; s > 0; s >>= 1) {
        if (threadIdx.x < s) red[threadIdx.x] += red[threadIdx.x + s];
        __syncthreads();
    }
    if (threadIdx.x == 0)
        out[0] = (float)(red[0] / (double)B);
}

// ---------------------------------------------------------------------------
extern "C" void kernel_launch(void* const* d_in, const int* in_sizes, int n_in,
                              void* d_out, int out_size) {
    const float* logits  = (const float*)d_in[0];
    const int*   targets = (const int*)d_in[1];
    const float* sim     = (const float*)d_in[2];
    float* out = (float*)d_out;

    zero_kernel<<<(C + 255) / 256, 256>>>();
    count_kernel<<<B / 1024, 1024>>>(targets);
    scan_kernel<<<1, 1024>>>();
    scatter_kernel<<<B / 1024, 1024>>>(targets);
    soft_ce_main_kernel<<<C * SPLIT, 256>>>(logits, sim);
    final_reduce_kernel<<<1, 256>>>(out);
}

// round 8
// speedup vs baseline: 1.5658x; 1.5658x over previous
#include <cuda_runtime.h>
#include <cuda_bf16.h>

constexpr int B = 65536;
constexpr int C = 1000;
constexpr float INV_NEG_T = -1.0f / 0.3f;   // -1/TEMPERATURE

constexpr int MAIN_THREADS = 256;
constexpr int WARPS_PER_BLOCK = MAIN_THREADS / 32;
constexpr int MAIN_BLOCKS = B / WARPS_PER_BLOCK;   // 8192

// Scratch (device globals — no allocation allowed)
__device__ __align__(16) __nv_bfloat16 g_Sb[C * C];   // raw exp(-sim/T), bf16, 2 MB
__device__ float g_invZ[C];                            // 1 / sum_c exp(-sim/T)
__device__ float g_partials[MAIN_BLOCKS];

// ---------------------------------------------------------------------------
// Prep: one pass over sim. e = exp(-sim/T) -> bf16 store; invZ[t] = 1/sum(e).
// One block per class row.
// ---------------------------------------------------------------------------
__global__ __launch_bounds__(256)
void prep_kernel(const float* __restrict__ sim) {
    const int t = blockIdx.x;
    const float* row = sim + (size_t)t * C;
    __shared__ float red[256];

    float lsum = 0.0f;
    const int i0 = threadIdx.x * 4;            // thread covers 4 consecutive
    if (i0 < C) {                               // 250 active threads
        const float4 v = *(const float4*)(row + i0);
        const float e0 = __expf(v.x * INV_NEG_T);
        const float e1 = __expf(v.y * INV_NEG_T);
        const float e2 = __expf(v.z * INV_NEG_T);
        const float e3 = __expf(v.w * INV_NEG_T);
        lsum = e0 + e1 + e2 + e3;
        __nv_bfloat162 p0 = __floats2bfloat162_rn(e0, e1);
        __nv_bfloat162 p1 = __floats2bfloat162_rn(e2, e3);
        uint2 packed = make_uint2(*(unsigned*)&p0, *(unsigned*)&p1);
        *(uint2*)(g_Sb + (size_t)t * C + i0) = packed;
    }

    red[threadIdx.x] = lsum;
    __syncthreads();
    for (int s = 128; s > 0; s >>= 1) {
        if (threadIdx.x < s) red[threadIdx.x] += red[threadIdx.x + s];
        __syncthreads();
    }
    if (threadIdx.x == 0)
        g_invZ[t] = 1.0f / red[0];
}

// ---------------------------------------------------------------------------
// Main: one warp per row. loss_b = log(sum exp x) - invZ[t] * dot(e_t, x).
// Logits: 250 float4 per row (DRAM). S: 125 float4-of-8-bf16 per row (L2-hot).
// Shared predicate j<125 covers both exactly (8*125 = 4*250 = 1000).
// ---------------------------------------------------------------------------
__global__ __launch_bounds__(MAIN_THREADS)
void soft_ce_main_kernel(const float* __restrict__ logits,
                         const int* __restrict__ targets) {
    const int warp = threadIdx.x >> 5;
    const int lane = threadIdx.x & 31;
    const int row = blockIdx.x * WARPS_PER_BLOCK + warp;

    int t = targets[row];
    t = (t < 0) ? 0 : ((t >= C) ? C - 1 : t);

    const float4* lp = (const float4*)(logits + (size_t)row * C);
    const float4* sp = (const float4*)(g_Sb + (size_t)t * C);
    const float invZ = g_invZ[t];

    float sum = 0.0f, dot = 0.0f;
    #pragma unroll
    for (int m = 0; m < 4; m++) {
        const int j = lane + m * 32;           // 125 float4 of bf16 per row
        if (j < 125) {
            const float4 x0 = lp[2 * j];
            const float4 x1 = lp[2 * j + 1];
            const float4 sraw = sp[j];
            const __nv_bfloat162* sb = (const __nv_bfloat162*)&sraw;
            const float2 s0 = __bfloat1622float2(sb[0]);
            const float2 s1 = __bfloat1622float2(sb[1]);
            const float2 s2 = __bfloat1622float2(sb[2]);
            const float2 s3 = __bfloat1622float2(sb[3]);

            sum += __expf(x0.x) + __expf(x0.y) + __expf(x0.z) + __expf(x0.w)
                 + __expf(x1.x) + __expf(x1.y) + __expf(x1.z) + __expf(x1.w);
            dot += s0.x * x0.x + s0.y * x0.y + s1.x * x0.z + s1.y * x0.w
                 + s2.x * x1.x + s2.y * x1.y + s3.x * x1.z + s3.y * x1.w;
        }
    }

    #pragma unroll
    for (int o = 16; o; o >>= 1) {
        sum += __shfl_xor_sync(0xffffffffu, sum, o);
        dot += __shfl_xor_sync(0xffffffffu, dot, o);
    }

    __shared__ float wsum[WARPS_PER_BLOCK];
    if (lane == 0)
        wsum[warp] = __logf(sum) - dot * invZ;
    __syncthreads();

    if (threadIdx.x == 0) {
        float acc = 0.0f;
        #pragma unroll
        for (int w = 0; w < WARPS_PER_BLOCK; w++) acc += wsum[w];
        g_partials[blockIdx.x] = acc;
    }
}

// ---------------------------------------------------------------------------
// Final reduce: 8192 partials -> mean loss.
// ---------------------------------------------------------------------------
__global__ __launch_bounds__(1024)
void final_reduce_kernel(float* __restrict__ out) {
    __shared__ double red[1024];
    double acc = 0.0;
    for (int i = threadIdx.x; i < MAIN_BLOCKS; i += 1024)
        acc += (double)g_partials[i];
    red[threadIdx.x] = acc;
    __syncthreads();
    for (int s = 512; s > 0; s >>= 1) {
        if (threadIdx.x < s) red[threadIdx.x] += red[threadIdx.x + s];
        __syncthreads();
    }
    if (threadIdx.x == 0)
        out[0] = (float)(red[0] / (double)B);
}

// ---------------------------------------------------------------------------
extern "C" void kernel_launch(void* const* d_in, const int* in_sizes, int n_in,
                              void* d_out, int out_size) {
    const float* logits  = (const float*)d_in[0];
    const int*   targets = (const int*)d_in[1];
    const float* sim     = (const float*)d_in[2];
    float* out = (float*)d_out;

    prep_kernel<<<C, 256>>>(sim);
    soft_ce_main_kernel<<<MAIN_BLOCKS, MAIN_THREADS>>>(logits, targets);
    final_reduce_kernel<<<1, 1024>>>(out);
}